// round 4
// baseline (speedup 1.0000x reference)
#include <cuda_runtime.h>
#include <stdint.h>

#define NMAX 50000
#define DD 128

// Scratch (no device allocs allowed)
__device__ int   g_mode;        // 1 = indices are int64, 0 = int32
__device__ float g_deg[NMAX];
__device__ float g_p[NMAX];
__device__ float g_q[NMAX];     // p * y   (hop-1 message value)
__device__ float g_r[NMAX];     // p * t   (hop-2 message value)
__device__ float g_acc1[NMAX];  // sum of q[src] per dst
__device__ float g_acc2[NMAX];  // sum of r[src] per dst

// ---------------------------------------------------------------------------
// K0: detect index dtype. If the buffer really holds int64 node ids, the first
// 32 values (read as int64) are all in [0, n). If it holds int32, each int64
// read pairs two random node ids -> value >= 2^32 almost surely.
__global__ void k_detect(const long long* __restrict__ edge, int n) {
    long long v = edge[threadIdx.x];          // 32 threads, 1 warp
    unsigned ok = __ballot_sync(0xffffffffu, v >= 0 && v < (long long)n);
    if (threadIdx.x == 0) g_mode = (ok == 0xffffffffu) ? 1 : 0;
}

__device__ __forceinline__ void load_edge(const long long* __restrict__ edge,
                                          int e, int e_cnt, int mode,
                                          int& src, int& dst) {
    if (mode) {
        src = (int)edge[e];
        dst = (int)edge[e_cnt + e];
    } else {
        const int* e32 = (const int*)edge;
        src = e32[e];
        dst = e32[e_cnt + e];
    }
}

// K1: deg[i] = 1 (self loop), zero accumulators
__global__ void k_init(int n) {
    int i = blockIdx.x * blockDim.x + threadIdx.x;
    if (i < n) {
        g_deg[i]  = 1.0f;
        g_acc1[i] = 0.0f;
        g_acc2[i] = 0.0f;
    }
}

// K2: deg[dst] += 1 for each edge
__global__ void k_count_deg(const long long* __restrict__ edge, int e_cnt, int n) {
    int e = blockIdx.x * blockDim.x + threadIdx.x;
    if (e < e_cnt) {
        int mode = g_mode;
        int src, dst;
        load_edge(edge, e, e_cnt, mode, src, dst);
        if ((unsigned)dst < (unsigned)n)
            atomicAdd(&g_deg[dst], 1.0f);
    }
}

// K3: warp per node: p = rsqrt(deg); y = dot(x[i], W); q = p*y
__global__ void k_proj(const float* __restrict__ x, const float* __restrict__ W, int n) {
    int warp = (blockIdx.x * blockDim.x + threadIdx.x) >> 5;
    int lane = threadIdx.x & 31;
    if (warp >= n) return;
    const float4* xv = (const float4*)(x + (size_t)warp * DD);
    const float4* wv = (const float4*)W;
    float4 a = xv[lane];
    float4 w = __ldg(&wv[lane]);
    float s = a.x * w.x + a.y * w.y + a.z * w.z + a.w * w.w;
    #pragma unroll
    for (int off = 16; off > 0; off >>= 1)
        s += __shfl_down_sync(0xffffffffu, s, off);
    if (lane == 0) {
        float p = rsqrtf(g_deg[warp]);
        g_p[warp] = p;
        g_q[warp] = p * s;
    }
}

// K4: hop1 edges: acc1[dst] += q[src]
__global__ void k_hop1(const long long* __restrict__ edge, int e_cnt, int n) {
    int e = blockIdx.x * blockDim.x + threadIdx.x;
    if (e < e_cnt) {
        int mode = g_mode;
        int src, dst;
        load_edge(edge, e, e_cnt, mode, src, dst);
        if ((unsigned)src < (unsigned)n && (unsigned)dst < (unsigned)n)
            atomicAdd(&g_acc1[dst], g_q[src]);
    }
}

// K5: r = p*p*(q + acc1)
__global__ void k_mid(int n) {
    int i = blockIdx.x * blockDim.x + threadIdx.x;
    if (i < n) {
        float p = g_p[i];
        g_r[i] = p * p * (g_q[i] + g_acc1[i]);
    }
}

// K6: hop2 edges: acc2[dst] += r[src]
__global__ void k_hop2(const long long* __restrict__ edge, int e_cnt, int n) {
    int e = blockIdx.x * blockDim.x + threadIdx.x;
    if (e < e_cnt) {
        int mode = g_mode;
        int src, dst;
        load_edge(edge, e, e_cnt, mode, src, dst);
        if ((unsigned)src < (unsigned)n && (unsigned)dst < (unsigned)n)
            atomicAdd(&g_acc2[dst], g_r[src]);
    }
}

// K7: out[i] = p*(r + acc2) + b
__global__ void k_final(float* __restrict__ out, const float* __restrict__ b, int n) {
    int i = blockIdx.x * blockDim.x + threadIdx.x;
    if (i < n) {
        out[i] = g_p[i] * (g_r[i] + g_acc2[i]) + b[0];
    }
}

extern "C" void kernel_launch(void* const* d_in, const int* in_sizes, int n_in,
                              void* d_out, int out_size) {
    const float*     x    = (const float*)d_in[0];       // [N, 128]
    const long long* edge = (const long long*)d_in[1];   // [2, E] indices
    const float*     W    = (const float*)d_in[2];       // [1, 128]
    const float*     b    = (const float*)d_in[3];       // [1]
    float*           out  = (float*)d_out;               // [N]

    int n = in_sizes[0] / DD;          // number of nodes
    if (n > NMAX) n = NMAX;
    const int e_cnt = in_sizes[1] / 2; // number of edges

    const int TPB = 256;
    const int nBlkN = (n + TPB - 1) / TPB;
    const int nBlkE = (e_cnt + TPB - 1) / TPB;
    const int nBlkW = (n * 32 + TPB - 1) / TPB;  // warp per node

    k_detect<<<1, 32>>>(edge, n);
    k_init<<<nBlkN, TPB>>>(n);
    k_count_deg<<<nBlkE, TPB>>>(edge, e_cnt, n);
    k_proj<<<nBlkW, TPB>>>(x, W, n);
    k_hop1<<<nBlkE, TPB>>>(edge, e_cnt, n);
    k_mid<<<nBlkN, TPB>>>(n);
    k_hop2<<<nBlkE, TPB>>>(edge, e_cnt, n);
    k_final<<<nBlkN, TPB>>>(out, b, n);
}

// round 5
// speedup vs baseline: 1.0244x; 1.0244x over previous
#include <cuda_runtime.h>
#include <stdint.h>

#define NMAX 50000
#define DD 128
#define NPW 8   // nodes per warp in k_proj

// Scratch (no device allocs allowed)
__device__ int   g_mode;        // 1 = indices are int64, 0 = int32
__device__ float g_deg[NMAX];
__device__ float g_p[NMAX];
__device__ float g_q[NMAX];     // p * y   (hop-1 message value)
__device__ float g_r[NMAX];     // p * t   (hop-2 message value)
__device__ float g_acc1[NMAX];  // sum of q[src] per dst
__device__ float g_acc2[NMAX];  // sum of r[src] per dst

// ---------------------------------------------------------------------------
// K1: detect dtype (warp 0 of block 0) + deg[i]=1 + zero accumulators
__global__ void k_init(const long long* __restrict__ edge, int n) {
    if (blockIdx.x == 0 && threadIdx.x < 32) {
        long long v = edge[threadIdx.x];
        unsigned ok = __ballot_sync(0xffffffffu, v >= 0 && v < (long long)n);
        if (threadIdx.x == 0) g_mode = (ok == 0xffffffffu) ? 1 : 0;
    }
    int i = blockIdx.x * blockDim.x + threadIdx.x;
    if (i < n) {
        g_deg[i]  = 1.0f;
        g_acc1[i] = 0.0f;
        g_acc2[i] = 0.0f;
    }
}

// ---------------------------------------------------------------------------
// K2: deg[dst] += 1.   4 edges per thread, vectorized dst reads.
__global__ void k_count_deg(const long long* __restrict__ edge, int e_cnt, int n) {
    int t = blockIdx.x * blockDim.x + threadIdx.x;
    int nvec = e_cnt >> 2;                     // groups of 4
    int mode = g_mode;
    if (t < nvec) {
        int d0, d1, d2, d3;
        if (mode) {
            const longlong2* dv = (const longlong2*)(edge + e_cnt) + 2 * t;
            longlong2 a = dv[0], b = dv[1];
            d0 = (int)a.x; d1 = (int)a.y; d2 = (int)b.x; d3 = (int)b.y;
        } else {
            const int* e32 = (const int*)edge;
            int4 d = ((const int4*)(e32 + e_cnt))[t];
            d0 = d.x; d1 = d.y; d2 = d.z; d3 = d.w;
        }
        if ((unsigned)d0 < (unsigned)n) atomicAdd(&g_deg[d0], 1.0f);
        if ((unsigned)d1 < (unsigned)n) atomicAdd(&g_deg[d1], 1.0f);
        if ((unsigned)d2 < (unsigned)n) atomicAdd(&g_deg[d2], 1.0f);
        if ((unsigned)d3 < (unsigned)n) atomicAdd(&g_deg[d3], 1.0f);
    } else if (t == nvec) {                    // tail (e_cnt % 4 edges)
        for (int e = nvec * 4; e < e_cnt; e++) {
            int dst;
            if (mode) dst = (int)edge[e_cnt + e];
            else      dst = ((const int*)edge)[e_cnt + e];
            if ((unsigned)dst < (unsigned)n) atomicAdd(&g_deg[dst], 1.0f);
        }
    }
}

// ---------------------------------------------------------------------------
// K3: warp handles NPW nodes: p = rsqrt(deg); y = dot(x, W); q = p*y
__global__ void k_proj(const float* __restrict__ x, const float* __restrict__ W, int n) {
    int warp = (blockIdx.x * blockDim.x + threadIdx.x) >> 5;
    int lane = threadIdx.x & 31;
    int base = warp * NPW;
    if (base >= n) return;

    float4 w = __ldg(&((const float4*)W)[lane]);

    float4 a[NPW];
    #pragma unroll
    for (int k = 0; k < NPW; k++) {
        int node = base + k;
        if (node < n)
            a[k] = ((const float4*)(x + (size_t)node * DD))[lane];
        else
            a[k] = make_float4(0.f, 0.f, 0.f, 0.f);
    }

    float s[NPW];
    #pragma unroll
    for (int k = 0; k < NPW; k++)
        s[k] = a[k].x * w.x + a[k].y * w.y + a[k].z * w.z + a[k].w * w.w;

    // interleaved warp reductions (pipelined shuffles)
    #pragma unroll
    for (int off = 16; off > 0; off >>= 1) {
        #pragma unroll
        for (int k = 0; k < NPW; k++)
            s[k] += __shfl_down_sync(0xffffffffu, s[k], off);
    }

    if (lane == 0) {
        #pragma unroll
        for (int k = 0; k < NPW; k++) {
            int node = base + k;
            if (node < n) {
                float p = rsqrtf(g_deg[node]);
                g_p[node] = p;
                g_q[node] = p * s[k];
            }
        }
    }
}

// ---------------------------------------------------------------------------
// Edge sweep: acc[dst] += val[src].  4 edges/thread, vectorized index loads.
__device__ __forceinline__ void edge_sweep(const long long* __restrict__ edge,
                                           int e_cnt, int n,
                                           const float* __restrict__ val,
                                           float* __restrict__ acc) {
    int t = blockIdx.x * blockDim.x + threadIdx.x;
    int nvec = e_cnt >> 2;
    int mode = g_mode;
    if (t < nvec) {
        int s0, s1, s2, s3, d0, d1, d2, d3;
        if (mode) {
            const longlong2* sv = (const longlong2*)edge + 2 * t;
            const longlong2* dv = (const longlong2*)(edge + e_cnt) + 2 * t;
            longlong2 sa = sv[0], sb = sv[1];
            longlong2 da = dv[0], db = dv[1];
            s0 = (int)sa.x; s1 = (int)sa.y; s2 = (int)sb.x; s3 = (int)sb.y;
            d0 = (int)da.x; d1 = (int)da.y; d2 = (int)db.x; d3 = (int)db.y;
        } else {
            const int* e32 = (const int*)edge;
            int4 sv = ((const int4*)e32)[t];
            int4 dv = ((const int4*)(e32 + e_cnt))[t];
            s0 = sv.x; s1 = sv.y; s2 = sv.z; s3 = sv.w;
            d0 = dv.x; d1 = dv.y; d2 = dv.z; d3 = dv.w;
        }
        bool ok0 = (unsigned)s0 < (unsigned)n && (unsigned)d0 < (unsigned)n;
        bool ok1 = (unsigned)s1 < (unsigned)n && (unsigned)d1 < (unsigned)n;
        bool ok2 = (unsigned)s2 < (unsigned)n && (unsigned)d2 < (unsigned)n;
        bool ok3 = (unsigned)s3 < (unsigned)n && (unsigned)d3 < (unsigned)n;
        // 4 independent gathers in flight
        float v0 = ok0 ? val[s0] : 0.f;
        float v1 = ok1 ? val[s1] : 0.f;
        float v2 = ok2 ? val[s2] : 0.f;
        float v3 = ok3 ? val[s3] : 0.f;
        if (ok0) atomicAdd(&acc[d0], v0);
        if (ok1) atomicAdd(&acc[d1], v1);
        if (ok2) atomicAdd(&acc[d2], v2);
        if (ok3) atomicAdd(&acc[d3], v3);
    } else if (t == nvec) {
        for (int e = nvec * 4; e < e_cnt; e++) {
            int src, dst;
            if (mode) { src = (int)edge[e]; dst = (int)edge[e_cnt + e]; }
            else { src = ((const int*)edge)[e]; dst = ((const int*)edge)[e_cnt + e]; }
            if ((unsigned)src < (unsigned)n && (unsigned)dst < (unsigned)n)
                atomicAdd(&acc[dst], val[src]);
        }
    }
}

__global__ void k_hop1(const long long* __restrict__ edge, int e_cnt, int n) {
    edge_sweep(edge, e_cnt, n, g_q, g_acc1);
}

__global__ void k_hop2(const long long* __restrict__ edge, int e_cnt, int n) {
    edge_sweep(edge, e_cnt, n, g_r, g_acc2);
}

// ---------------------------------------------------------------------------
// K5: r = p*p*(q + acc1)
__global__ void k_mid(int n) {
    int i = blockIdx.x * blockDim.x + threadIdx.x;
    if (i < n) {
        float p = g_p[i];
        g_r[i] = p * p * (g_q[i] + g_acc1[i]);
    }
}

// K7: out[i] = p*(r + acc2) + b
__global__ void k_final(float* __restrict__ out, const float* __restrict__ b, int n) {
    int i = blockIdx.x * blockDim.x + threadIdx.x;
    if (i < n) {
        out[i] = g_p[i] * (g_r[i] + g_acc2[i]) + b[0];
    }
}

extern "C" void kernel_launch(void* const* d_in, const int* in_sizes, int n_in,
                              void* d_out, int out_size) {
    const float*     x    = (const float*)d_in[0];       // [N, 128]
    const long long* edge = (const long long*)d_in[1];   // [2, E] indices
    const float*     W    = (const float*)d_in[2];       // [1, 128]
    const float*     b    = (const float*)d_in[3];       // [1]
    float*           out  = (float*)d_out;               // [N]

    int n = in_sizes[0] / DD;
    if (n > NMAX) n = NMAX;
    const int e_cnt = in_sizes[1] / 2;

    const int TPB = 256;
    const int nBlkN = (n + TPB - 1) / TPB;
    const int nThrE = e_cnt / 4 + 1;                      // 4 edges / thread (+tail)
    const int nBlkE = (nThrE + TPB - 1) / TPB;
    const int nWarps = (n + NPW - 1) / NPW;
    const int nBlkW = (nWarps * 32 + TPB - 1) / TPB;

    k_init<<<nBlkN, TPB>>>(edge, n);
    k_count_deg<<<nBlkE, TPB>>>(edge, e_cnt, n);
    k_proj<<<nBlkW, TPB>>>(x, W, n);
    k_hop1<<<nBlkE, TPB>>>(edge, e_cnt, n);
    k_mid<<<nBlkN, TPB>>>(n);
    k_hop2<<<nBlkE, TPB>>>(edge, e_cnt, n);
    k_final<<<nBlkN, TPB>>>(out, b, n);
}

// round 7
// speedup vs baseline: 1.0500x; 1.0250x over previous
#include <cuda_runtime.h>
#include <stdint.h>

#define NMAX 50000
#define DD 128
#define NPW 8   // nodes per warp in k_proj
#define EPT 8   // edges per thread in edge sweeps

// Scratch (no device allocs allowed)
__device__ int   g_mode;        // 1 = indices are int64, 0 = int32
__device__ float g_deg[NMAX];
__device__ float g_p[NMAX];
__device__ float g_q[NMAX];     // p * y   (hop-1 message value)
__device__ float g_r[NMAX];     // p * t   (hop-2 message value)
__device__ float g_acc1[NMAX];  // sum of q[src] per dst
__device__ float g_acc2[NMAX];  // sum of r[src] per dst

// ---------------------------------------------------------------------------
// K1: detect dtype (warp 0 of block 0) + deg[i]=1 + zero accumulators
__global__ void k_init(const long long* __restrict__ edge, int n) {
    if (blockIdx.x == 0 && threadIdx.x < 32) {
        long long v = edge[threadIdx.x];
        unsigned ok = __ballot_sync(0xffffffffu, v >= 0 && v < (long long)n);
        if (threadIdx.x == 0) g_mode = (ok == 0xffffffffu) ? 1 : 0;
    }
    int i = blockIdx.x * blockDim.x + threadIdx.x;
    if (i < n) {
        g_deg[i]  = 1.0f;
        g_acc1[i] = 0.0f;
        g_acc2[i] = 0.0f;
    }
}

// ---------------------------------------------------------------------------
// Load EPT=8 indices starting at edge index base (mode-dependent).
__device__ __forceinline__ void load_idx8(const long long* __restrict__ edge,
                                          int base, int mode, int off,
                                          int idx[EPT]) {
    if (mode) {
        const longlong2* v = (const longlong2*)(edge + off) + (base >> 1);
        longlong2 a = v[0], b = v[1], c = v[2], d = v[3];
        idx[0] = (int)a.x; idx[1] = (int)a.y;
        idx[2] = (int)b.x; idx[3] = (int)b.y;
        idx[4] = (int)c.x; idx[5] = (int)c.y;
        idx[6] = (int)d.x; idx[7] = (int)d.y;
    } else {
        const int* e32 = (const int*)edge;
        const int4* v = (const int4*)(e32 + off) + (base >> 2);
        int4 a = v[0], b = v[1];
        idx[0] = a.x; idx[1] = a.y; idx[2] = a.z; idx[3] = a.w;
        idx[4] = b.x; idx[5] = b.y; idx[6] = b.z; idx[7] = b.w;
    }
}

// ---------------------------------------------------------------------------
// K2: deg[dst] += 1.   EPT edges per thread.
__global__ void k_count_deg(const long long* __restrict__ edge, int e_cnt, int n) {
    int t = blockIdx.x * blockDim.x + threadIdx.x;
    int nvec = e_cnt / EPT;
    int mode = g_mode;
    if (t < nvec) {
        int d[EPT];
        load_idx8(edge, t * EPT, mode, e_cnt, d);
        #pragma unroll
        for (int k = 0; k < EPT; k++)
            if ((unsigned)d[k] < (unsigned)n) atomicAdd(&g_deg[d[k]], 1.0f);
    } else if (t == nvec) {
        for (int e = nvec * EPT; e < e_cnt; e++) {
            int dst = mode ? (int)edge[e_cnt + e] : ((const int*)edge)[e_cnt + e];
            if ((unsigned)dst < (unsigned)n) atomicAdd(&g_deg[dst], 1.0f);
        }
    }
}

// ---------------------------------------------------------------------------
// K3: warp handles NPW nodes: p = rsqrt(deg); y = dot(x, W); q = p*y
__global__ void k_proj(const float* __restrict__ x, const float* __restrict__ W, int n) {
    int warp = (blockIdx.x * blockDim.x + threadIdx.x) >> 5;
    int lane = threadIdx.x & 31;
    int base = warp * NPW;
    if (base >= n) return;

    float4 w = __ldg(&((const float4*)W)[lane]);

    float4 a[NPW];
    #pragma unroll
    for (int k = 0; k < NPW; k++) {
        int node = base + k;
        if (node < n)
            a[k] = ((const float4*)(x + (size_t)node * DD))[lane];
        else
            a[k] = make_float4(0.f, 0.f, 0.f, 0.f);
    }

    float s[NPW];
    #pragma unroll
    for (int k = 0; k < NPW; k++)
        s[k] = a[k].x * w.x + a[k].y * w.y + a[k].z * w.z + a[k].w * w.w;

    #pragma unroll
    for (int off = 16; off > 0; off >>= 1) {
        #pragma unroll
        for (int k = 0; k < NPW; k++)
            s[k] += __shfl_down_sync(0xffffffffu, s[k], off);
    }

    if (lane == 0) {
        #pragma unroll
        for (int k = 0; k < NPW; k++) {
            int node = base + k;
            if (node < n) {
                float p = rsqrtf(g_deg[node]);
                g_p[node] = p;
                g_q[node] = p * s[k];
            }
        }
    }
}

// ---------------------------------------------------------------------------
// Edge sweep: acc[dst] += val[src].  EPT edges/thread, all index loads first,
// then all gathers in flight, then fire-and-forget atomics.
__device__ __forceinline__ void edge_sweep(const long long* __restrict__ edge,
                                           int e_cnt, int n,
                                           const float* __restrict__ val,
                                           float* __restrict__ acc) {
    int t = blockIdx.x * blockDim.x + threadIdx.x;
    int nvec = e_cnt / EPT;
    int mode = g_mode;
    if (t < nvec) {
        int s[EPT], d[EPT];
        load_idx8(edge, t * EPT, mode, 0, s);
        load_idx8(edge, t * EPT, mode, e_cnt, d);
        bool ok[EPT];
        float v[EPT];
        #pragma unroll
        for (int k = 0; k < EPT; k++) {
            ok[k] = (unsigned)s[k] < (unsigned)n && (unsigned)d[k] < (unsigned)n;
            v[k] = ok[k] ? val[s[k]] : 0.f;      // independent gathers
        }
        #pragma unroll
        for (int k = 0; k < EPT; k++)
            if (ok[k]) atomicAdd(&acc[d[k]], v[k]);
    } else if (t == nvec) {
        for (int e = nvec * EPT; e < e_cnt; e++) {
            int src = mode ? (int)edge[e] : ((const int*)edge)[e];
            int dst = mode ? (int)edge[e_cnt + e] : ((const int*)edge)[e_cnt + e];
            if ((unsigned)src < (unsigned)n && (unsigned)dst < (unsigned)n)
                atomicAdd(&acc[dst], val[src]);
        }
    }
}

__global__ void k_hop1(const long long* __restrict__ edge, int e_cnt, int n) {
    edge_sweep(edge, e_cnt, n, g_q, g_acc1);
}

__global__ void k_hop2(const long long* __restrict__ edge, int e_cnt, int n) {
    edge_sweep(edge, e_cnt, n, g_r, g_acc2);
}

// ---------------------------------------------------------------------------
// K5: r = p*p*(q + acc1)
__global__ void k_mid(int n) {
    int i = blockIdx.x * blockDim.x + threadIdx.x;
    if (i < n) {
        float p = g_p[i];
        g_r[i] = p * p * (g_q[i] + g_acc1[i]);
    }
}

// K7: out[i] = p*(r + acc2) + b
__global__ void k_final(float* __restrict__ out, const float* __restrict__ b, int n) {
    int i = blockIdx.x * blockDim.x + threadIdx.x;
    if (i < n) {
        out[i] = g_p[i] * (g_r[i] + g_acc2[i]) + b[0];
    }
}

extern "C" void kernel_launch(void* const* d_in, const int* in_sizes, int n_in,
                              void* d_out, int out_size) {
    const float*     x    = (const float*)d_in[0];       // [N, 128]
    const long long* edge = (const long long*)d_in[1];   // [2, E] indices
    const float*     W    = (const float*)d_in[2];       // [1, 128]
    const float*     b    = (const float*)d_in[3];       // [1]
    float*           out  = (float*)d_out;               // [N]

    int n = in_sizes[0] / DD;
    if (n > NMAX) n = NMAX;
    const int e_cnt = in_sizes[1] / 2;

    const int TPB = 256;
    const int nBlkN = (n + TPB - 1) / TPB;
    const int nThrE = e_cnt / EPT + 1;
    const int nBlkE = (nThrE + TPB - 1) / TPB;
    const int nWarps = (n + NPW - 1) / NPW;
    const int nBlkW = (nWarps * 32 + TPB - 1) / TPB;

    k_init<<<nBlkN, TPB>>>(edge, n);
    k_count_deg<<<nBlkE, TPB>>>(edge, e_cnt, n);
    k_proj<<<nBlkW, TPB>>>(x, W, n);
    k_hop1<<<nBlkE, TPB>>>(edge, e_cnt, n);
    k_mid<<<nBlkN, TPB>>>(n);
    k_hop2<<<nBlkE, TPB>>>(edge, e_cnt, n);
    k_final<<<nBlkN, TPB>>>(out, b, n);
}